// round 1
// baseline (speedup 1.0000x reference)
#include <cuda_runtime.h>
#include <cstdint>
#include <cstddef>

// Problem constants
#define Bb 32
#define Ll 2048
#define Uu 512
#define Hh 8
#define HDd 64
#define NPOS (Bb * Ll)      // 65536
#define MCH 1536            // q|k|v output channels concatenated

// ---------------------------------------------------------------------------
// Device scratch (allocation-free rule: __device__ globals)
// ---------------------------------------------------------------------------
__device__ __align__(16) float    g_Y[(size_t)NPOS * MCH];      // 384 MB conv outputs [n][1536]
__device__ __align__(16) unsigned g_Wpack[3u * 512u * 1536u];   // tf32-rounded weights [tau][k][m]
__device__ float g_bias[MCH];
__device__ float g_cmax[Bb * MCH];                              // per (b, channel) max over L
__device__ float g_att[Bb * Hh * HDd];                          // attention output

// ---------------------------------------------------------------------------
// Helpers
// ---------------------------------------------------------------------------
__device__ __forceinline__ unsigned f2tf32(float f) {
    unsigned u;
    asm("cvt.rna.tf32.f32 %0, %1;" : "=r"(u) : "f"(f));
    return u;
}

__device__ __forceinline__ void mma_tf32(float c[4],
                                         unsigned a0, unsigned a1, unsigned a2, unsigned a3,
                                         unsigned b0, unsigned b1) {
    asm volatile(
        "mma.sync.aligned.m16n8k8.row.col.f32.tf32.tf32.f32 "
        "{%0,%1,%2,%3}, {%4,%5,%6,%7}, {%8,%9}, {%0,%1,%2,%3};\n"
        : "+f"(c[0]), "+f"(c[1]), "+f"(c[2]), "+f"(c[3])
        : "r"(a0), "r"(a1), "r"(a2), "r"(a3), "r"(b0), "r"(b1));
}

// ---------------------------------------------------------------------------
// Kernel 1: repack conv weights (U,U,3) x3 -> g_Wpack[tau][k][m] (tf32-rounded)
// ---------------------------------------------------------------------------
__global__ void repack_kernel(const float* __restrict__ Wq, const float* __restrict__ bq,
                              const float* __restrict__ Wk, const float* __restrict__ bk,
                              const float* __restrict__ Wv, const float* __restrict__ bv) {
    int gid = blockIdx.x * blockDim.x + threadIdx.x;
    if (gid < MCH) {
        g_bias[gid] = gid < 512 ? bq[gid] : (gid < 1024 ? bk[gid - 512] : bv[gid - 1024]);
    }
    const int per_conv = 512 * 512 * 3;
    if (gid >= 3 * per_conv) return;
    int conv = gid / per_conv;
    int rem  = gid % per_conv;
    int m    = rem / 1536;      // out channel within conv
    int rest = rem % 1536;
    int k    = rest / 3;        // in channel
    int tau  = rest % 3;        // tap
    const float* W = (conv == 0) ? Wq : ((conv == 1) ? Wk : Wv);
    float v = W[m * 1536 + k * 3 + tau];
    g_Wpack[(size_t)(tau * 512 + k) * MCH + conv * 512 + m] = f2tf32(v);
}

// ---------------------------------------------------------------------------
// Kernel 2: fused qkv conv as tf32 tensor-core GEMM
//   Y[n][m] = bias[m] + sum_tau sum_k Wpack[tau][k][m] * t[n + tau - 1][k]
// Block tile: 128 (n) x 128 (m), K chunks of 32, 8 warps, warp tile 64x32.
// ---------------------------------------------------------------------------
__global__ __launch_bounds__(256) void conv_gemm_kernel(const float* __restrict__ t) {
    __shared__ unsigned As[128 * 36];   // [i][k], pad 36 -> conflict-free frag LDS
    __shared__ unsigned Bs[32 * 136];   // [k][m], pad 136 -> conflict-free frag LDS

    const int tid  = threadIdx.x;
    const int m0   = blockIdx.x * 128;
    const int n0   = blockIdx.y * 128;
    const int b    = n0 >> 11;          // n0 / 2048 (tiles never straddle batches)
    const int l0   = n0 & 2047;
    const int lane = tid & 31;
    const int w    = tid >> 5;
    const int g    = lane >> 2;
    const int tg   = lane & 3;
    const int wm   = w & 1;             // 2 warps over n
    const int wn   = w >> 1;            // 4 warps over m

    float acc[4][4][4];
#pragma unroll
    for (int i = 0; i < 4; i++)
#pragma unroll
        for (int j = 0; j < 4; j++)
#pragma unroll
            for (int e = 0; e < 4; e++) acc[i][j][e] = 0.f;

    const float* tb = t + (size_t)b * Ll * Uu;

    for (int tau = 0; tau < 3; tau++) {
        const int sh = tau - 1;
        for (int kc = 0; kc < 16; kc++) {   // 512 / 32
            const int k0 = kc * 32;
            // --- load A tile: 128 rows x 32 k (shifted by tap, zero-padded) ---
#pragma unroll
            for (int p = 0; p < 4; p++) {
                int idx = p * 256 + tid;
                int i   = idx >> 3;
                int kq  = (idx & 7) * 4;
                int l   = l0 + i + sh;
                float4 v = make_float4(0.f, 0.f, 0.f, 0.f);
                if (l >= 0 && l < Ll)
                    v = *(const float4*)(tb + (size_t)l * Uu + k0 + kq);
                uint4 u;
                u.x = f2tf32(v.x); u.y = f2tf32(v.y);
                u.z = f2tf32(v.z); u.w = f2tf32(v.w);
                *(uint4*)&As[i * 36 + kq] = u;
            }
            // --- load B tile: 32 k x 128 m ---
#pragma unroll
            for (int p = 0; p < 4; p++) {
                int idx = p * 256 + tid;
                int kk  = idx >> 5;
                int mq  = (idx & 31) * 4;
                uint4 v = *(const uint4*)(g_Wpack + (size_t)(tau * 512 + k0 + kk) * MCH + m0 + mq);
                *(uint4*)&Bs[kk * 136 + mq] = v;
            }
            __syncthreads();

#pragma unroll
            for (int k8 = 0; k8 < 4; k8++) {
                const int kb = k8 * 8;
                unsigned a[4][4], bb[4][2];
#pragma unroll
                for (int mf = 0; mf < 4; mf++) {
                    int rb = wm * 64 + mf * 16;
                    a[mf][0] = As[(rb + g) * 36 + kb + tg];
                    a[mf][1] = As[(rb + g + 8) * 36 + kb + tg];
                    a[mf][2] = As[(rb + g) * 36 + kb + tg + 4];
                    a[mf][3] = As[(rb + g + 8) * 36 + kb + tg + 4];
                }
#pragma unroll
                for (int nf = 0; nf < 4; nf++) {
                    int cb = wn * 32 + nf * 8 + g;
                    bb[nf][0] = Bs[(kb + tg) * 136 + cb];
                    bb[nf][1] = Bs[(kb + tg + 4) * 136 + cb];
                }
#pragma unroll
                for (int mf = 0; mf < 4; mf++)
#pragma unroll
                    for (int nf = 0; nf < 4; nf++)
                        mma_tf32(acc[mf][nf], a[mf][0], a[mf][1], a[mf][2], a[mf][3],
                                 bb[nf][0], bb[nf][1]);
            }
            __syncthreads();
        }
    }

    // --- epilogue: add bias, store to g_Y[n][m] ---
#pragma unroll
    for (int mf = 0; mf < 4; mf++) {
#pragma unroll
        for (int nf = 0; nf < 4; nf++) {
            int row = n0 + wm * 64 + mf * 16 + g;
            int col = m0 + wn * 32 + nf * 8 + 2 * tg;
            float b0 = g_bias[col], b1 = g_bias[col + 1];
            float* o0 = g_Y + (size_t)row * MCH + col;
            float* o1 = g_Y + (size_t)(row + 8) * MCH + col;
            o0[0] = acc[mf][nf][0] + b0;
            o0[1] = acc[mf][nf][1] + b1;
            o1[0] = acc[mf][nf][2] + b0;
            o1[1] = acc[mf][nf][3] + b1;
        }
    }
}

// ---------------------------------------------------------------------------
// Kernel 3: per-(b, channel) max over L  -> g_cmax[b][c]
// ---------------------------------------------------------------------------
__global__ void reduce_max_kernel() {
    int gid = blockIdx.x * blockDim.x + threadIdx.x;   // 32*1536
    if (gid >= Bb * MCH) return;
    int b = gid / MCH;
    int c = gid % MCH;
    const float* p = g_Y + (size_t)b * Ll * MCH + c;
    float m = -3.4e38f;
    for (int l = 0; l < Ll; l++) m = fmaxf(m, p[(size_t)l * MCH]);
    g_cmax[gid] = m;
}

// ---------------------------------------------------------------------------
// Kernel 4: attention per (b, h). 2049 keys = [global max key, maxpool3 keys].
// ---------------------------------------------------------------------------
__global__ __launch_bounds__(256) void attn_kernel(const int* __restrict__ gmask,
                                                   const int* __restrict__ tmask) {
    __shared__ float q_s[64];
    __shared__ float lg[2049];
    __shared__ float red[256];

    const int bh   = blockIdx.x;
    const int b    = bh >> 3;
    const int h    = bh & 7;
    const int tid  = threadIdx.x;
    const int lane = tid & 31;
    const int w    = tid >> 5;

    if (tid < 64) q_s[tid] = g_cmax[b * MCH + h * HDd + tid];
    __syncthreads();

    const float scale = 0.04419417382415922f;   // 1/sqrt(512)
    const float gmf   = (float)gmask[b];

    const float* Yk = g_Y + (size_t)b * Ll * MCH + 512 + h * HDd;

    // logits
    for (int j = w; j <= Ll; j += 8) {
        float k1, k2;
        if (j == 0) {
            k1 = g_cmax[b * MCH + 512 + h * HDd + lane];
            k2 = g_cmax[b * MCH + 512 + h * HDd + lane + 32];
        } else {
            int l = j - 1;
            const float* r = Yk + (size_t)l * MCH;
            k1 = r[lane];
            k2 = r[lane + 32];
            if (l > 0)      { k1 = fmaxf(k1, r[lane - MCH]);      k2 = fmaxf(k2, r[lane + 32 - MCH]); }
            if (l < Ll - 1) { k1 = fmaxf(k1, r[lane + MCH]);      k2 = fmaxf(k2, r[lane + 32 + MCH]); }
        }
        float p = q_s[lane] * k1 + q_s[lane + 32] * k2;
#pragma unroll
        for (int o = 16; o; o >>= 1) p += __shfl_down_sync(0xffffffffu, p, o);
        if (lane == 0) {
            int mk = (j == 0) ? gmask[b] : tmask[b * Ll + (j - 1)];
            lg[j] = mk ? p * scale : -1e30f;
        }
    }
    __syncthreads();

    // softmax: max
    float lm = -1e30f;
    for (int j = tid; j < Ll + 1; j += 256) lm = fmaxf(lm, lg[j]);
    red[tid] = lm;
    __syncthreads();
    for (int s = 128; s; s >>= 1) {
        if (tid < s) red[tid] = fmaxf(red[tid], red[tid + s]);
        __syncthreads();
    }
    float mx = red[0];
    __syncthreads();

    // softmax: exp + sum
    float ls = 0.f;
    for (int j = tid; j < Ll + 1; j += 256) {
        float e = expf(lg[j] - mx);
        lg[j] = e;
        ls += e;
    }
    red[tid] = ls;
    __syncthreads();
    for (int s = 128; s; s >>= 1) {
        if (tid < s) red[tid] += red[tid + s];
        __syncthreads();
    }
    float sinv = 1.0f / red[0];
    __syncthreads();

    // weighted sum over values (maxpool3 on the fly)
    const int d   = tid & 63;
    const int grp = tid >> 6;
    const float* Yv = g_Y + (size_t)b * Ll * MCH + 1024 + h * HDd + d;
    float acc = 0.f;
    for (int j = grp; j <= Ll; j += 4) {
        float v;
        if (j == 0) {
            v = g_cmax[b * MCH + 1024 + h * HDd + d];
        } else {
            int l = j - 1;
            const float* r = Yv + (size_t)l * MCH;
            v = r[0];
            if (l > 0)      v = fmaxf(v, r[-MCH]);
            if (l < Ll - 1) v = fmaxf(v, r[MCH]);
        }
        acc += lg[j] * v;
    }
    red[tid] = acc;
    __syncthreads();
    if (tid < 64) {
        float o = (red[tid] + red[tid + 64] + red[tid + 128] + red[tid + 192]) * sinv * gmf;
        g_att[(b * Hh + h) * HDd + tid] = o;
    }
}

// ---------------------------------------------------------------------------
// Kernel 5: head-mix (Wh 8x8) + output 1x1 conv (Wo 512x512)
// ---------------------------------------------------------------------------
__global__ __launch_bounds__(512) void final_kernel(const float* __restrict__ Wh,
                                                    const float* __restrict__ bh,
                                                    const float* __restrict__ Wo,
                                                    const float* __restrict__ bo,
                                                    float* __restrict__ out) {
    const int b   = blockIdx.x;
    const int tid = threadIdx.x;     // 512 = u = oh*64 + d
    __shared__ float mid[512];

    const int oh = tid >> 6;
    const int d  = tid & 63;
    float s = bh[oh];
#pragma unroll
    for (int i = 0; i < 8; i++) s += Wh[oh * 8 + i] * g_att[(b * Hh + i) * HDd + d];
    mid[tid] = s;
    __syncthreads();

    float o = bo[tid];
    const float* wr = Wo + (size_t)tid * 512;
#pragma unroll 8
    for (int i = 0; i < 512; i++) o += wr[i] * mid[i];
    out[b * 512 + tid] = o;
}

// ---------------------------------------------------------------------------
// Launch
// ---------------------------------------------------------------------------
extern "C" void kernel_launch(void* const* d_in, const int* in_sizes, int n_in,
                              void* d_out, int out_size) {
    const float* t     = (const float*)d_in[0];
    // d_in[1] = g (unused by reference)
    const int*   gmask = (const int*)d_in[2];
    const int*   tmask = (const int*)d_in[3];
    const float* Wq    = (const float*)d_in[4];
    const float* bq    = (const float*)d_in[5];
    const float* Wk    = (const float*)d_in[6];
    const float* bk    = (const float*)d_in[7];
    const float* Wv    = (const float*)d_in[8];
    const float* bv    = (const float*)d_in[9];
    const float* Wh    = (const float*)d_in[10];
    const float* bh    = (const float*)d_in[11];
    const float* Wo    = (const float*)d_in[12];
    const float* bo    = (const float*)d_in[13];
    float* out = (float*)d_out;

    repack_kernel<<<9216, 256>>>(Wq, bq, Wk, bk, Wv, bv);
    conv_gemm_kernel<<<dim3(MCH / 128, NPOS / 128), 256>>>(t);
    reduce_max_kernel<<<(Bb * MCH + 255) / 256, 256>>>();
    attn_kernel<<<Bb * Hh, 256>>>(gmask, tmask);
    final_kernel<<<Bb, 512>>>(Wh, bh, Wo, bo, out);
}

// round 3
// speedup vs baseline: 2.1621x; 2.1621x over previous
#include <cuda_runtime.h>
#include <cuda_fp16.h>
#include <cstdint>
#include <cstddef>

// Problem constants
#define Bb 32
#define Ll 2048
#define Uu 512
#define Hh 8
#define HDd 64
#define NPOS (Bb * Ll)      // 65536
#define MCH 1536            // q|k|v channels (cmax indexing)
#define KVW 1024            // stored channels (k,v only)

// GEMM config: M = positions, N = channels, K = 3*512
#define TM 128
#define TN 128
#define BK 64
#define NCHUNK 24           // 1536 / 64
#define STAGE 32768         // 16KB A + 16KB B
#define NSTAGE 3

// ---------------------------------------------------------------------------
// Device scratch
// ---------------------------------------------------------------------------
__device__ __align__(16) __half g_Th[(size_t)NPOS * Uu];      // fp16(t), 64MB
__device__ __align__(16) __half g_Wh[(size_t)MCH * MCH];      // fp16 W [m][tau*512+k]
__device__ __align__(16) float  g_Y[(size_t)NPOS * KVW];      // k|v conv out, 256MB
__device__ float g_bias[MCH];
__device__ float g_cmax[Bb * MCH];
__device__ float g_att[Bb * Hh * HDd];

// ---------------------------------------------------------------------------
// Helpers
// ---------------------------------------------------------------------------
__device__ __forceinline__ void cp16(uint32_t dst, const void* src, bool valid) {
    int sz = valid ? 16 : 0;
    asm volatile("cp.async.cg.shared.global [%0], [%1], 16, %2;\n"
                 :: "r"(dst), "l"(src), "r"(sz));
}
#define CP_COMMIT() asm volatile("cp.async.commit_group;" ::: "memory")
#define CP_WAIT(n)  asm volatile("cp.async.wait_group %0;" :: "n"(n) : "memory")

__device__ __forceinline__ uint32_t su32(const void* p) {
    uint32_t a;
    asm("{ .reg .u64 t; cvta.to.shared.u64 t, %1; cvt.u32.u64 %0, t; }" : "=r"(a) : "l"(p));
    return a;
}

__device__ __forceinline__ void mma_f16(float c[4],
                                        uint32_t a0, uint32_t a1, uint32_t a2, uint32_t a3,
                                        uint32_t b0, uint32_t b1) {
    asm volatile(
        "mma.sync.aligned.m16n8k16.row.col.f32.f16.f16.f32 "
        "{%0,%1,%2,%3}, {%4,%5,%6,%7}, {%8,%9}, {%0,%1,%2,%3};\n"
        : "+f"(c[0]), "+f"(c[1]), "+f"(c[2]), "+f"(c[3])
        : "r"(a0), "r"(a1), "r"(a2), "r"(a3), "r"(b0), "r"(b1));
}

__device__ __forceinline__ void atomicMaxF(float* a, float v) {
    if (v >= 0.f) atomicMax((int*)a, __float_as_int(v));
    else          atomicMin((unsigned*)a, __float_as_uint(v));
}

// fragment LDS from a swizzled tile: row stride 128B, 16B-chunk XOR (row&7)
__device__ __forceinline__ uint32_t lds_frag(const char* base, int row, int h) {
    // h = half index within row (0..63); pairs are 4B aligned (h even)
    int chunk = h >> 3;
    int off   = (h & 7) * 2;
    return *(const uint32_t*)(base + row * 128 + ((chunk ^ (row & 7)) << 4) + off);
}

// ---------------------------------------------------------------------------
// t -> fp16
// ---------------------------------------------------------------------------
__global__ void tconv_kernel(const float* __restrict__ t) {
    size_t gid = (size_t)blockIdx.x * blockDim.x + threadIdx.x;   // float4 index
    if (gid >= (size_t)NPOS * Uu / 4) return;
    float4 v = ((const float4*)t)[gid];
    __half2 h0 = __floats2half2_rn(v.x, v.y);
    __half2 h1 = __floats2half2_rn(v.z, v.w);
    ((uint2*)g_Th)[gid] = make_uint2(*(uint32_t*)&h0, *(uint32_t*)&h1);
}

// ---------------------------------------------------------------------------
// weights -> fp16 [m][tau*512+k] (K-major rows), bias
// ---------------------------------------------------------------------------
__global__ void repack_kernel(const float* __restrict__ Wq, const float* __restrict__ bq,
                              const float* __restrict__ Wk, const float* __restrict__ bk,
                              const float* __restrict__ Wv, const float* __restrict__ bv) {
    int gid = blockIdx.x * blockDim.x + threadIdx.x;
    if (gid < MCH)
        g_bias[gid] = gid < 512 ? bq[gid] : (gid < 1024 ? bk[gid - 512] : bv[gid - 1024]);
    if (gid >= MCH * MCH) return;
    int mg   = gid / MCH;
    int kk   = gid % MCH;
    int tau  = kk / 512;
    int k    = kk % 512;
    int conv = mg / 512;
    int m    = mg % 512;
    const float* W = (conv == 0) ? Wq : ((conv == 1) ? Wk : Wv);
    g_Wh[gid] = __float2half_rn(W[m * 1536 + k * 3 + tau]);
}

__global__ void cmax_init_kernel() {
    int gid = blockIdx.x * blockDim.x + threadIdx.x;
    if (gid < Bb * MCH) ((unsigned*)g_cmax)[gid] = 0xff800000u;   // -inf
}

// ---------------------------------------------------------------------------
// fused qkv conv: fp16 HMMA GEMM, 128x128 tile, 3-stage cp.async pipeline.
// Epilogue: +bias, per-channel max -> g_cmax, store k/v rows to g_Y.
// ---------------------------------------------------------------------------
__global__ __launch_bounds__(256, 2) void conv_hmma_kernel() {
    extern __shared__ __align__(128) char dsmem[];   // 3 * 32KB
    __shared__ float bias_s[TN];

    const int tid  = threadIdx.x;
    const int wid  = tid >> 5;
    const int lane = tid & 31;
    const int g    = lane >> 2;
    const int tg   = lane & 3;
    const int wm   = wid >> 1;          // 0..3: M strip of 32
    const int wn   = wid & 1;           // 0..1: N strip of 64
    const int m0   = blockIdx.x * TN;
    const int n0   = blockIdx.y * TM;
    const int b    = n0 >> 11;
    const int l0   = n0 & 2047;

    if (tid < TN) bias_s[tid] = g_bias[m0 + tid];

    const uint32_t smem0 = su32(dsmem);

    // ---- chunk loader ----
    auto load_chunk = [&](int c, int slot) {
        const int tau = c >> 3;
        const int k0  = (c & 7) * BK;
        const uint32_t abase = smem0 + (uint32_t)slot * STAGE;
        const uint32_t bbase = abase + 16384u;
#pragma unroll
        for (int p = 0; p < 4; p++) {
            int idx = p * 256 + tid;       // 0..1023
            int row = idx >> 3;
            int j   = idx & 7;
            int l   = l0 + row + tau - 1;
            bool ok = (l >= 0 && l < Ll);
            const void* src = g_Th + ((size_t)(b * Ll + (ok ? l : 0))) * Uu + k0 + j * 8;
            cp16(abase + (uint32_t)(row * 128 + ((j ^ (row & 7)) << 4)), src, ok);
        }
#pragma unroll
        for (int p = 0; p < 4; p++) {
            int idx = p * 256 + tid;
            int row = idx >> 3;
            int j   = idx & 7;
            const void* src = g_Wh + (size_t)(m0 + row) * MCH + tau * 512 + k0 + j * 8;
            cp16(bbase + (uint32_t)(row * 128 + ((j ^ (row & 7)) << 4)), src, true);
        }
    };

    float acc[2][8][4];
#pragma unroll
    for (int i = 0; i < 2; i++)
#pragma unroll
        for (int j = 0; j < 8; j++)
#pragma unroll
            for (int e = 0; e < 4; e++) acc[i][j][e] = 0.f;

    // prologue
    load_chunk(0, 0); CP_COMMIT();
    load_chunk(1, 1); CP_COMMIT();

    for (int i = 0; i < NCHUNK; i++) {
        if (i + 1 < NCHUNK) { CP_WAIT(1); } else { CP_WAIT(0); }
        __syncthreads();
        if (i + 2 < NCHUNK) { load_chunk(i + 2, (i + 2) % NSTAGE); CP_COMMIT(); }

        const char* Ab = dsmem + (i % NSTAGE) * STAGE;
        const char* Bbse = Ab + 16384;
#pragma unroll
        for (int kk = 0; kk < 4; kk++) {
            const int kb = kk * 16;
            uint32_t a[2][4];
#pragma unroll
            for (int mf = 0; mf < 2; mf++) {
                int r0 = wm * 32 + mf * 16 + g;
                a[mf][0] = lds_frag(Ab, r0,     kb + 2 * tg);
                a[mf][1] = lds_frag(Ab, r0 + 8, kb + 2 * tg);
                a[mf][2] = lds_frag(Ab, r0,     kb + 8 + 2 * tg);
                a[mf][3] = lds_frag(Ab, r0 + 8, kb + 8 + 2 * tg);
            }
            uint32_t bf[8][2];
#pragma unroll
            for (int nf = 0; nf < 8; nf++) {
                int rn = wn * 64 + nf * 8 + g;
                bf[nf][0] = lds_frag(Bbse, rn, kb + 2 * tg);
                bf[nf][1] = lds_frag(Bbse, rn, kb + 8 + 2 * tg);
            }
#pragma unroll
            for (int mf = 0; mf < 2; mf++)
#pragma unroll
                for (int nf = 0; nf < 8; nf++)
                    mma_f16(acc[mf][nf], a[mf][0], a[mf][1], a[mf][2], a[mf][3],
                            bf[nf][0], bf[nf][1]);
        }
    }

    // ---- epilogue: bias, store k/v, channel max ----
    const bool do_store = (m0 >= 512);
#pragma unroll
    for (int nf = 0; nf < 8; nf++) {
        const int col = m0 + wn * 64 + nf * 8 + 2 * tg;
        const float b0 = bias_s[col - m0], b1 = bias_s[col - m0 + 1];
        float cm0 = -3.4e38f, cm1 = -3.4e38f;
#pragma unroll
        for (int mf = 0; mf < 2; mf++) {
            float v0 = acc[mf][nf][0] + b0;
            float v1 = acc[mf][nf][1] + b1;
            float v2 = acc[mf][nf][2] + b0;
            float v3 = acc[mf][nf][3] + b1;
            if (do_store) {
                size_t n = (size_t)n0 + wm * 32 + mf * 16 + g;
                float* p = g_Y + n * KVW + (col - 512);
                *(float2*)p = make_float2(v0, v1);
                *(float2*)(p + (size_t)8 * KVW) = make_float2(v2, v3);
            }
            cm0 = fmaxf(cm0, fmaxf(v0, v2));
            cm1 = fmaxf(cm1, fmaxf(v1, v3));
        }
#pragma unroll
        for (int o = 4; o <= 16; o <<= 1) {
            cm0 = fmaxf(cm0, __shfl_xor_sync(0xffffffffu, cm0, o));
            cm1 = fmaxf(cm1, __shfl_xor_sync(0xffffffffu, cm1, o));
        }
        if (lane < 4) {
            atomicMaxF(&g_cmax[b * MCH + col], cm0);
            atomicMaxF(&g_cmax[b * MCH + col + 1], cm1);
        }
    }
}

// ---------------------------------------------------------------------------
// attention per (b, h): 2049 keys = [global max key, maxpool3 keys]
// g_Y layout: [n][1024], K cols 0..511, V cols 512..1023
// ---------------------------------------------------------------------------
__global__ __launch_bounds__(512) void attn_kernel(const int* __restrict__ gmask,
                                                   const int* __restrict__ tmask) {
    __shared__ float q_s[64];
    __shared__ float lg[2049];
    __shared__ float red[512];

    const int bh   = blockIdx.x;
    const int b    = bh >> 3;
    const int h    = bh & 7;
    const int tid  = threadIdx.x;
    const int lane = tid & 31;
    const int w    = tid >> 5;          // 0..15

    if (tid < 64) q_s[tid] = g_cmax[b * MCH + h * HDd + tid];
    __syncthreads();

    const float scale = 0.04419417382415922f;   // 1/sqrt(512)
    const float gmf   = (float)gmask[b];

    const float* Yk = g_Y + (size_t)b * Ll * KVW + h * HDd;

    // logits (warp per key)
    for (int j = w; j <= Ll; j += 16) {
        float k1, k2;
        if (j == 0) {
            k1 = g_cmax[b * MCH + 512 + h * HDd + lane];
            k2 = g_cmax[b * MCH + 512 + h * HDd + lane + 32];
        } else {
            int l = j - 1;
            const float* r = Yk + (size_t)l * KVW;
            k1 = r[lane];
            k2 = r[lane + 32];
            if (l > 0)      { k1 = fmaxf(k1, r[lane - KVW]);     k2 = fmaxf(k2, r[lane + 32 - KVW]); }
            if (l < Ll - 1) { k1 = fmaxf(k1, r[lane + KVW]);     k2 = fmaxf(k2, r[lane + 32 + KVW]); }
        }
        float p = q_s[lane] * k1 + q_s[lane + 32] * k2;
#pragma unroll
        for (int o = 16; o; o >>= 1) p += __shfl_down_sync(0xffffffffu, p, o);
        if (lane == 0) {
            int mk = (j == 0) ? gmask[b] : tmask[b * Ll + (j - 1)];
            lg[j] = mk ? p * scale : -1e30f;
        }
    }
    __syncthreads();

    // softmax max
    float lm = -1e30f;
    for (int j = tid; j < Ll + 1; j += 512) lm = fmaxf(lm, lg[j]);
    red[tid] = lm;
    __syncthreads();
    for (int s = 256; s; s >>= 1) {
        if (tid < s) red[tid] = fmaxf(red[tid], red[tid + s]);
        __syncthreads();
    }
    float mx = red[0];
    __syncthreads();

    // exp + sum
    float ls = 0.f;
    for (int j = tid; j < Ll + 1; j += 512) {
        float e = expf(lg[j] - mx);
        lg[j] = e;
        ls += e;
    }
    red[tid] = ls;
    __syncthreads();
    for (int s = 256; s; s >>= 1) {
        if (tid < s) red[tid] += red[tid + s];
        __syncthreads();
    }
    float sinv = 1.0f / red[0];
    __syncthreads();

    // weighted sum over values (maxpool3 on the fly), 8 groups of 64
    const int d   = tid & 63;
    const int grp = tid >> 6;
    const float* Yv = g_Y + (size_t)b * Ll * KVW + 512 + h * HDd + d;
    float acc = 0.f;
    for (int j = grp; j <= Ll; j += 8) {
        float v;
        if (j == 0) {
            v = g_cmax[b * MCH + 1024 + h * HDd + d];
        } else {
            int l = j - 1;
            const float* r = Yv + (size_t)l * KVW;
            v = r[0];
            if (l > 0)      v = fmaxf(v, r[-KVW]);
            if (l < Ll - 1) v = fmaxf(v, r[KVW]);
        }
        acc += lg[j] * v;
    }
    red[tid] = acc;
    __syncthreads();
    if (tid < 64) {
        float o = 0.f;
#pragma unroll
        for (int k = 0; k < 8; k++) o += red[tid + 64 * k];
        g_att[(b * Hh + h) * HDd + tid] = o * sinv * gmf;
    }
}

// ---------------------------------------------------------------------------
// head-mix (Wh 8x8) + output 1x1 conv (Wo 512x512)
// ---------------------------------------------------------------------------
__global__ __launch_bounds__(512) void final_kernel(const float* __restrict__ Wh,
                                                    const float* __restrict__ bh,
                                                    const float* __restrict__ Wo,
                                                    const float* __restrict__ bo,
                                                    float* __restrict__ out) {
    const int b   = blockIdx.x;
    const int tid = threadIdx.x;
    __shared__ float mid[512];

    const int oh = tid >> 6;
    const int d  = tid & 63;
    float s = bh[oh];
#pragma unroll
    for (int i = 0; i < 8; i++) s += Wh[oh * 8 + i] * g_att[(b * Hh + i) * HDd + d];
    mid[tid] = s;
    __syncthreads();

    float o = bo[tid];
    const float* wr = Wo + (size_t)tid * 512;
#pragma unroll 8
    for (int i = 0; i < 512; i++) o += wr[i] * mid[i];
    out[b * 512 + tid] = o;
}

// ---------------------------------------------------------------------------
// Launch
// ---------------------------------------------------------------------------
extern "C" void kernel_launch(void* const* d_in, const int* in_sizes, int n_in,
                              void* d_out, int out_size) {
    const float* t     = (const float*)d_in[0];
    const int*   gmask = (const int*)d_in[2];
    const int*   tmask = (const int*)d_in[3];
    const float* Wq    = (const float*)d_in[4];
    const float* bq    = (const float*)d_in[5];
    const float* Wk    = (const float*)d_in[6];
    const float* bk    = (const float*)d_in[7];
    const float* Wv    = (const float*)d_in[8];
    const float* bv    = (const float*)d_in[9];
    const float* Wh    = (const float*)d_in[10];
    const float* bh    = (const float*)d_in[11];
    const float* Wo    = (const float*)d_in[12];
    const float* bo    = (const float*)d_in[13];
    float* out = (float*)d_out;

    cudaFuncSetAttribute(conv_hmma_kernel, cudaFuncAttributeMaxDynamicSharedMemorySize,
                         NSTAGE * STAGE);

    tconv_kernel<<<(int)(((size_t)NPOS * Uu / 4 + 255) / 256), 256>>>(t);
    repack_kernel<<<(MCH * MCH + 255) / 256, 256>>>(Wq, bq, Wk, bk, Wv, bv);
    cmax_init_kernel<<<(Bb * MCH + 255) / 256, 256>>>();
    conv_hmma_kernel<<<dim3(MCH / TN, NPOS / TM), 256, NSTAGE * STAGE>>>();
    attn_kernel<<<Bb * Hh, 512>>>(gmask, tmask);
    final_kernel<<<Bb, 512>>>(Wh, bh, Wo, bo, out);
}